// round 3
// baseline (speedup 1.0000x reference)
#include <cuda_runtime.h>
#include <math.h>

#define PDIM    4354
#define PSTRIDE 4356   // padded row stride (multiple of 4 for float4 alignment)
#define BATCH   32
#define SEQ     64

// Double-buffered theta [batch][PSTRIDE], plus scalar carries.
__device__ float g_theta[2][BATCH * PSTRIDE];
__device__ float g_u[BATCH];
__device__ float g_xprev[BATCH];

// ---------------------------------------------------------------------------
// Init: broadcast theta_init across batch, zero x_prev.
// ---------------------------------------------------------------------------
__global__ void init_kernel(const float* __restrict__ theta_init) {
    int idx = blockIdx.x * blockDim.x + threadIdx.x;
    if (idx < BATCH * PDIM) {
        int b = idx / PDIM;
        int p = idx - b * PDIM;
        g_theta[0][b * PSTRIDE + p] = theta_init[p];
    }
    if (idx < BATCH) g_xprev[idx] = 0.0f;
}

// ---------------------------------------------------------------------------
// Prep kernel (per step t): for each batch b (one warp per batch):
//   mu_sigma_t = MLP(theta_t, t/SEQ); write mean/std outputs at column t;
//   x_hat = noise*std + mean; x_t = (t < inference_start) ? xs[b][t] : x_hat;
//   u[b] = x_t - x_prev[b]; x_prev[b] = x_t.
// MLP: dims (1,32), 4x (32,32), (32,2); silu between; tanh(mean); exp(0.5*clip(logvar)).
// ---------------------------------------------------------------------------
__global__ __launch_bounds__(1024) void prep_kernel(
    const float* __restrict__ xs,
    const float* __restrict__ noise,
    const int*   __restrict__ inf_start_p,
    float*       __restrict__ out,
    int t, int par)
{
    int b    = threadIdx.x >> 5;   // warp id = batch
    int lane = threadIdx.x & 31;
    const float* __restrict__ th = g_theta[par] + b * PSTRIDE;

    float x = (float)t / (float)SEQ;

    // Layer 0: (1 -> 32). W at th[0..31], bias th[32..63].
    float y = x * th[lane] + th[32 + lane];
    y = y / (1.0f + expf(-y));   // silu

    // Hidden layers 1..4: (32 -> 32). base = 64 + l*1056; W row-major (o,i); bias at base+1024.
    #pragma unroll
    for (int l = 0; l < 4; l++) {
        int base = 64 + l * 1056;
        const float4* wp = reinterpret_cast<const float4*>(th + base + lane * 32);
        float4 w[8];
        #pragma unroll
        for (int q = 0; q < 8; q++) w[q] = wp[q];

        float acc = th[base + 1024 + lane];  // bias
        #pragma unroll
        for (int q = 0; q < 8; q++) {
            float yi0 = __shfl_sync(0xffffffffu, y, q * 4 + 0);
            float yi1 = __shfl_sync(0xffffffffu, y, q * 4 + 1);
            float yi2 = __shfl_sync(0xffffffffu, y, q * 4 + 2);
            float yi3 = __shfl_sync(0xffffffffu, y, q * 4 + 3);
            acc += w[q].x * yi0;
            acc += w[q].y * yi1;
            acc += w[q].z * yi2;
            acc += w[q].w * yi3;
        }
        y = acc / (1.0f + expf(-acc));  // silu
    }

    // Final layer: (32 -> 2). W at th[4288..4351], bias th[4352..4353].
    // All lanes compute both outputs (uniform; loads broadcast).
    float s0 = 0.0f, s1 = 0.0f;
    #pragma unroll
    for (int ii = 0; ii < 32; ii++) {
        float yi = __shfl_sync(0xffffffffu, y, ii);
        s0 += yi * th[4288 + ii];
        s1 += yi * th[4320 + ii];
    }

    if (lane == 0) {
        float mean = tanhf(s0 + th[4352]);
        float lv   = s1 + th[4353];
        lv = fminf(fmaxf(lv, -4.0f), 4.0f);
        float sd = expf(0.5f * lv);

        // Outputs: means.T (32,64) then stds.T (32,64), row-major [b][t].
        out[b * SEQ + t] = mean;
        out[BATCH * SEQ + b * SEQ + t] = sd;

        float nz   = noise[t * BATCH + b];     // noise (seq, batch, 1)
        float xhat = nz * sd + mean;
        float xt   = (t < *inf_start_p) ? xs[b * SEQ + t] : xhat;
        g_u[b]     = xt - g_xprev[b];
        g_xprev[b] = xt;
    }
}

// ---------------------------------------------------------------------------
// Step GEMM: theta_next = clip(theta @ A^T + u * B^T, -1, 1)
//   C[b][p] = sum_k theta[b][k] * A[p][k] + u[b]*B[p]
// TILE_P = 32, 128 threads, micro-tile 4p x 2b, K chunks of 32 with register
// prefetch (hide L2 latency behind the FFMA inner loop).
// ---------------------------------------------------------------------------
__global__ __launch_bounds__(128) void gemm_kernel(
    const float* __restrict__ A,
    const float* __restrict__ Bv,
    int par)
{
    const float* __restrict__ th  = g_theta[par];
    float*       __restrict__ onx = g_theta[par ^ 1];

    __shared__ float tS[32][33];
    __shared__ float aS[32][33];

    int tid = threadIdx.x;
    int p0  = blockIdx.x * 32;
    int pi  = tid & 7;    // p group: p = p0 + pi + 8*i
    int bj  = tid >> 3;   // b group: b = bj + 16*j

    int c  = tid & 31;    // fixed column this thread loads
    int r0 = tid >> 5;    // base row (0..3), rows r0 + 4*it

    float acc[4][2];
    #pragma unroll
    for (int i = 0; i < 4; i++)
        #pragma unroll
        for (int j = 0; j < 2; j++) acc[i][j] = 0.0f;

    // Prefetch first K chunk into registers.
    float tReg[8], aReg[8];
    {
        int k = c;  // k0 = 0, always < PDIM
        #pragma unroll
        for (int it = 0; it < 8; it++) {
            int r  = r0 + 4 * it;
            int pr = p0 + r;
            tReg[it] = th[r * PSTRIDE + k];
            aReg[it] = (pr < PDIM) ? A[pr * PDIM + k] : 0.0f;
        }
    }

    for (int k0 = 0; k0 < PDIM; k0 += 32) {
        // Commit prefetched chunk to smem.
        #pragma unroll
        for (int it = 0; it < 8; it++) {
            int r = r0 + 4 * it;
            tS[r][c] = tReg[it];
            aS[r][c] = aReg[it];
        }
        __syncthreads();

        // Prefetch next chunk (overlaps with inner loop).
        int kn = k0 + 32 + c;
        if (k0 + 32 < PDIM) {
            bool kok = (kn < PDIM);
            #pragma unroll
            for (int it = 0; it < 8; it++) {
                int r  = r0 + 4 * it;
                int pr = p0 + r;
                tReg[it] = kok ? th[r * PSTRIDE + kn] : 0.0f;
                aReg[it] = (kok && pr < PDIM) ? A[pr * PDIM + kn] : 0.0f;
            }
        }

        // Inner product over this chunk. Last chunk (k0=4352) has only 2 valid
        // columns; guard via zero-padding is avoided by masking here.
        int kw = PDIM - k0;
        if (kw >= 32) {
            #pragma unroll
            for (int kk = 0; kk < 32; kk++) {
                float tv0 = tS[bj][kk];
                float tv1 = tS[bj + 16][kk];
                float a0  = aS[pi][kk];
                float a1  = aS[pi + 8][kk];
                float a2  = aS[pi + 16][kk];
                float a3  = aS[pi + 24][kk];
                acc[0][0] += a0 * tv0;  acc[0][1] += a0 * tv1;
                acc[1][0] += a1 * tv0;  acc[1][1] += a1 * tv1;
                acc[2][0] += a2 * tv0;  acc[2][1] += a2 * tv1;
                acc[3][0] += a3 * tv0;  acc[3][1] += a3 * tv1;
            }
        } else {
            for (int kk = 0; kk < kw; kk++) {
                float tv0 = tS[bj][kk];
                float tv1 = tS[bj + 16][kk];
                float a0  = aS[pi][kk];
                float a1  = aS[pi + 8][kk];
                float a2  = aS[pi + 16][kk];
                float a3  = aS[pi + 24][kk];
                acc[0][0] += a0 * tv0;  acc[0][1] += a0 * tv1;
                acc[1][0] += a1 * tv0;  acc[1][1] += a1 * tv1;
                acc[2][0] += a2 * tv0;  acc[2][1] += a2 * tv1;
                acc[3][0] += a3 * tv0;  acc[3][1] += a3 * tv1;
            }
        }
        __syncthreads();
    }

    // Epilogue: rank-1 update + clip + store.
    float u0 = g_u[bj];
    float u1 = g_u[bj + 16];
    #pragma unroll
    for (int i = 0; i < 4; i++) {
        int p = p0 + pi + 8 * i;
        if (p < PDIM) {
            float bp = Bv[p];
            float v0 = acc[i][0] + u0 * bp;
            float v1 = acc[i][1] + u1 * bp;
            v0 = fminf(fmaxf(v0, -1.0f), 1.0f);
            v1 = fminf(fmaxf(v1, -1.0f), 1.0f);
            onx[bj * PSTRIDE + p]        = v0;
            onx[(bj + 16) * PSTRIDE + p] = v1;
        }
    }
}

// ---------------------------------------------------------------------------
// kernel_launch: init + 64 x (prep, gemm). All graph-capturable launches.
// Inputs (metadata order): xs(2048) f32, noise(2048) f32, theta_init(4354) f32,
//                          A(4354*4354) f32, B(4354) f32, inference_start(1) i32.
// Output: float[4096] = concat(means.T (32,64), stds.T (32,64)).
// ---------------------------------------------------------------------------
extern "C" void kernel_launch(void* const* d_in, const int* in_sizes, int n_in,
                              void* d_out, int out_size) {
    const float* xs         = (const float*)d_in[0];
    const float* noise      = (const float*)d_in[1];
    const float* theta_init = (const float*)d_in[2];
    const float* A          = (const float*)d_in[3];
    const float* Bv         = (const float*)d_in[4];
    const int*   inf_start  = (const int*)d_in[5];
    float*       out        = (float*)d_out;

    init_kernel<<<(BATCH * PDIM + 255) / 256, 256>>>(theta_init);

    for (int t = 0; t < SEQ; t++) {
        int par = t & 1;
        prep_kernel<<<1, 1024>>>(xs, noise, inf_start, out, t, par);
        gemm_kernel<<<(PDIM + 31) / 32, 128>>>(A, Bv, par);
    }
}

// round 4
// speedup vs baseline: 1.2304x; 1.2304x over previous
#include <cuda_runtime.h>
#include <math.h>

#define PDIM    4354
#define PAD     4384            // 137 * 32, padded dim for A and theta rows
#define PAD4    (PAD / 4)       // 1096 float4 per row
#define NCH     (PAD / 32)      // 137 K-chunks of 32
#define BATCH   32
#define SEQ     64

// Static device scratch (no allocations allowed).
__device__ __align__(16) float g_A[PAD * PAD];            // padded copy of A (zeros outside PDIM)
__device__ __align__(16) float g_theta[2][BATCH * PAD];   // double-buffered theta, zero-padded cols
__device__ float g_u[BATCH];
__device__ float g_xprev[BATCH];

// ---------------------------------------------------------------------------
// Init 1: pad-copy A into g_A (zeros in padding). Grid-stride.
// ---------------------------------------------------------------------------
__global__ void init_A_kernel(const float* __restrict__ A) {
    long long total = (long long)PAD * PAD;
    for (long long idx = blockIdx.x * (long long)blockDim.x + threadIdx.x;
         idx < total; idx += (long long)gridDim.x * blockDim.x) {
        int p = (int)(idx / PAD);
        int k = (int)(idx - (long long)p * PAD);
        g_A[idx] = (p < PDIM && k < PDIM) ? A[(long long)p * PDIM + k] : 0.0f;
    }
}

// ---------------------------------------------------------------------------
// Init 2: theta buffers (buf0 = broadcast theta_init, padding zero; buf1 = 0),
// x_prev = 0.
// ---------------------------------------------------------------------------
__global__ void init_theta_kernel(const float* __restrict__ theta_init) {
    int total = 2 * BATCH * PAD;
    for (int idx = blockIdx.x * blockDim.x + threadIdx.x;
         idx < total; idx += gridDim.x * blockDim.x) {
        int buf = idx / (BATCH * PAD);
        int rem = idx - buf * (BATCH * PAD);
        int k = rem % PAD;
        float v = 0.0f;
        if (buf == 0 && k < PDIM) v = theta_init[k];
        ((float*)g_theta)[idx] = v;
    }
    int idx0 = blockIdx.x * blockDim.x + threadIdx.x;
    if (idx0 < BATCH) g_xprev[idx0] = 0.0f;
}

// ---------------------------------------------------------------------------
// Prep kernel (per step t): ONE BLOCK PER BATCH (32 blocks x 32 threads).
// MLP(theta_b, t/SEQ) -> mean/std outputs at column t; u[b] = x_t - x_prev[b].
// ---------------------------------------------------------------------------
__global__ __launch_bounds__(32) void prep_kernel(
    const float* __restrict__ xs,
    const float* __restrict__ noise,
    const int*   __restrict__ inf_start_p,
    float*       __restrict__ out,
    int t, int par)
{
    int b    = blockIdx.x;
    int lane = threadIdx.x;
    const float* __restrict__ th = g_theta[par] + b * PAD;

    float x = (float)t / (float)SEQ;

    // Layer 0: (1 -> 32). W at th[0..31], bias th[32..63].
    float y = x * th[lane] + th[32 + lane];
    y = y / (1.0f + expf(-y));   // silu

    // Hidden layers 1..4: base = 64 + l*1056; W row-major (o,i); bias at base+1024.
    #pragma unroll
    for (int l = 0; l < 4; l++) {
        int base = 64 + l * 1056;
        const float4* wp = reinterpret_cast<const float4*>(th + base + lane * 32);
        float4 w[8];
        #pragma unroll
        for (int q = 0; q < 8; q++) w[q] = wp[q];

        float acc = th[base + 1024 + lane];  // bias
        #pragma unroll
        for (int q = 0; q < 8; q++) {
            float yi0 = __shfl_sync(0xffffffffu, y, q * 4 + 0);
            float yi1 = __shfl_sync(0xffffffffu, y, q * 4 + 1);
            float yi2 = __shfl_sync(0xffffffffu, y, q * 4 + 2);
            float yi3 = __shfl_sync(0xffffffffu, y, q * 4 + 3);
            acc = fmaf(w[q].x, yi0, acc);
            acc = fmaf(w[q].y, yi1, acc);
            acc = fmaf(w[q].z, yi2, acc);
            acc = fmaf(w[q].w, yi3, acc);
        }
        y = acc / (1.0f + expf(-acc));  // silu
    }

    // Final layer: (32 -> 2). W at th[4288..4351], bias th[4352..4353].
    float s0 = 0.0f, s1 = 0.0f;
    #pragma unroll
    for (int ii = 0; ii < 32; ii++) {
        float yi = __shfl_sync(0xffffffffu, y, ii);
        s0 = fmaf(yi, th[4288 + ii], s0);
        s1 = fmaf(yi, th[4320 + ii], s1);
    }

    if (lane == 0) {
        float mean = tanhf(s0 + th[4352]);
        float lv   = s1 + th[4353];
        lv = fminf(fmaxf(lv, -4.0f), 4.0f);
        float sd = expf(0.5f * lv);

        out[b * SEQ + t] = mean;
        out[BATCH * SEQ + b * SEQ + t] = sd;

        float nz   = noise[t * BATCH + b];     // noise (seq, batch, 1)
        float xhat = nz * sd + mean;
        float xt   = (t < *inf_start_p) ? xs[b * SEQ + t] : xhat;
        g_u[b]     = xt - g_xprev[b];
        g_xprev[b] = xt;
    }
}

// ---------------------------------------------------------------------------
// Step GEMM: theta_next = clip(theta @ A^T + u * B^T, -1, 1)
// 137 blocks x 128 threads; tile 32p x 32b; micro-tile 4p x 2b.
// float4 smem (row stride 9 float4 = 36 floats -> conflict-free), double
// buffered, register prefetch. 137 uniform K-chunks of 32 (no masking).
// ---------------------------------------------------------------------------
#define DOT4(ac, a, t)                      \
    ac = fmaf((a).x, (t).x, ac);            \
    ac = fmaf((a).y, (t).y, ac);            \
    ac = fmaf((a).z, (t).z, ac);            \
    ac = fmaf((a).w, (t).w, ac);

__global__ __launch_bounds__(128) void gemm_kernel(
    const float* __restrict__ Bv,
    int par)
{
    const float4* __restrict__ th4 = reinterpret_cast<const float4*>(g_theta[par]);
    const float4* __restrict__ A4  = reinterpret_cast<const float4*>(g_A);
    float*        __restrict__ onx = g_theta[par ^ 1];

    __shared__ float4 tS[2][32][9];
    __shared__ float4 aS[2][32][9];

    int tid = threadIdx.x;
    int p0  = blockIdx.x * 32;
    int r   = tid >> 3;          // 0..15 : load row
    int c4  = tid & 7;           // 0..7  : load float4 column
    int pi  = tid & 7;           // compute: p = p0 + pi + 8*i
    int bj  = tid >> 3;          // compute: b = bj, bj+16

    float acc[4][2];
    #pragma unroll
    for (int i = 0; i < 4; i++) { acc[i][0] = 0.0f; acc[i][1] = 0.0f; }

    int rowT0 = r * PAD4;
    int rowT1 = (r + 16) * PAD4;
    int rowA0 = (p0 + r) * PAD4;
    int rowA1 = (p0 + r + 16) * PAD4;

    // Prologue: chunk 0 -> buffer 0.
    {
        float4 t0 = th4[rowT0 + c4];
        float4 t1 = th4[rowT1 + c4];
        float4 a0 = A4[rowA0 + c4];
        float4 a1 = A4[rowA1 + c4];
        tS[0][r][c4]      = t0;
        tS[0][r + 16][c4] = t1;
        aS[0][r][c4]      = a0;
        aS[0][r + 16][c4] = a1;
    }
    __syncthreads();

    for (int ch = 0; ch < NCH; ch++) {
        int cur = ch & 1;

        // Prefetch next chunk (global -> regs) before compute.
        float4 t0, t1, a0, a1;
        bool more = (ch + 1 < NCH);
        if (more) {
            int kb = (ch + 1) * 8 + c4;
            t0 = th4[rowT0 + kb];
            t1 = th4[rowT1 + kb];
            a0 = A4[rowA0 + kb];
            a1 = A4[rowA1 + kb];
        }

        // Compute on current buffer: 8 x (6 LDS.128 + 32 FFMA).
        #pragma unroll
        for (int k4 = 0; k4 < 8; k4++) {
            float4 tv0 = tS[cur][bj][k4];
            float4 tv1 = tS[cur][bj + 16][k4];
            float4 av0 = aS[cur][pi][k4];
            float4 av1 = aS[cur][pi + 8][k4];
            float4 av2 = aS[cur][pi + 16][k4];
            float4 av3 = aS[cur][pi + 24][k4];
            DOT4(acc[0][0], av0, tv0);  DOT4(acc[0][1], av0, tv1);
            DOT4(acc[1][0], av1, tv0);  DOT4(acc[1][1], av1, tv1);
            DOT4(acc[2][0], av2, tv0);  DOT4(acc[2][1], av2, tv1);
            DOT4(acc[3][0], av3, tv0);  DOT4(acc[3][1], av3, tv1);
        }

        // Commit prefetched chunk to the other buffer.
        if (more) {
            int nxt = cur ^ 1;
            tS[nxt][r][c4]      = t0;
            tS[nxt][r + 16][c4] = t1;
            aS[nxt][r][c4]      = a0;
            aS[nxt][r + 16][c4] = a1;
        }
        __syncthreads();
    }

    // Epilogue: rank-1 update + clip + store (padding columns stay zero).
    float u0 = g_u[bj];
    float u1 = g_u[bj + 16];
    #pragma unroll
    for (int i = 0; i < 4; i++) {
        int p = p0 + pi + 8 * i;
        if (p < PDIM) {
            float bp = Bv[p];
            float v0 = fmaf(u0, bp, acc[i][0]);
            float v1 = fmaf(u1, bp, acc[i][1]);
            v0 = fminf(fmaxf(v0, -1.0f), 1.0f);
            v1 = fminf(fmaxf(v1, -1.0f), 1.0f);
            onx[bj * PAD + p]        = v0;
            onx[(bj + 16) * PAD + p] = v1;
        }
    }
}

// ---------------------------------------------------------------------------
// kernel_launch: init + 64 x (prep, gemm). All graph-capturable launches.
// Inputs: xs(2048) f32, noise(2048) f32, theta_init(4354) f32,
//         A(4354*4354) f32, B(4354) f32, inference_start(1) i32.
// Output: float[4096] = concat(means.T (32,64), stds.T (32,64)).
// ---------------------------------------------------------------------------
extern "C" void kernel_launch(void* const* d_in, const int* in_sizes, int n_in,
                              void* d_out, int out_size) {
    const float* xs         = (const float*)d_in[0];
    const float* noise      = (const float*)d_in[1];
    const float* theta_init = (const float*)d_in[2];
    const float* A          = (const float*)d_in[3];
    const float* Bv         = (const float*)d_in[4];
    const int*   inf_start  = (const int*)d_in[5];
    float*       out        = (float*)d_out;

    init_A_kernel<<<2048, 256>>>(A);
    init_theta_kernel<<<1096, 256>>>(theta_init);

    for (int t = 0; t < SEQ; t++) {
        int par = t & 1;
        prep_kernel<<<BATCH, 32>>>(xs, noise, inf_start, out, t, par);
        gemm_kernel<<<NCH, 128>>>(Bv, par);
    }
}

// round 6
// speedup vs baseline: 1.7717x; 1.4400x over previous
#include <cuda_runtime.h>
#include <math.h>

#define PDIM    4354
#define PAD     4384            // 137 * 32, padded dim for A and theta rows
#define PAD4    (PAD / 4)       // 1096 float4 per row
#define NCH     (PAD / 32)      // 137 K-chunks of 32
#define BATCH   32
#define SEQ     64

// Static device scratch (no allocations allowed).
__device__ __align__(16) float g_A[PAD * PAD];            // padded copy of A (zeros outside PDIM)
__device__ __align__(16) float g_theta[2][BATCH * PAD];   // double-buffered theta, zero-padded cols
__device__ float g_u[BATCH];
__device__ float g_xprev[BATCH];

// ---------------------------------------------------------------------------
// Init 1: pad-copy A into g_A (zeros in padding). Grid-stride.
// ---------------------------------------------------------------------------
__global__ void init_A_kernel(const float* __restrict__ A) {
    long long total = (long long)PAD * PAD;
    for (long long idx = blockIdx.x * (long long)blockDim.x + threadIdx.x;
         idx < total; idx += (long long)gridDim.x * blockDim.x) {
        int p = (int)(idx / PAD);
        int k = (int)(idx - (long long)p * PAD);
        g_A[idx] = (p < PDIM && k < PDIM) ? A[(long long)p * PDIM + k] : 0.0f;
    }
}

// ---------------------------------------------------------------------------
// Init 2: theta buffers (buf0 = broadcast theta_init, padding zero; buf1 = 0),
// x_prev = 0.
// ---------------------------------------------------------------------------
__global__ void init_theta_kernel(const float* __restrict__ theta_init) {
    int total = 2 * BATCH * PAD;
    for (int idx = blockIdx.x * blockDim.x + threadIdx.x;
         idx < total; idx += gridDim.x * blockDim.x) {
        int buf = idx / (BATCH * PAD);
        int rem = idx - buf * (BATCH * PAD);
        int k = rem % PAD;
        float v = 0.0f;
        if (buf == 0 && k < PDIM) v = theta_init[k];
        ((float*)g_theta)[idx] = v;
    }
    int idx0 = blockIdx.x * blockDim.x + threadIdx.x;
    if (idx0 < BATCH) g_xprev[idx0] = 0.0f;
}

// ---------------------------------------------------------------------------
// Prep kernel (per step t): ONE BLOCK PER BATCH (32 blocks x 32 threads).
// ---------------------------------------------------------------------------
__global__ __launch_bounds__(32) void prep_kernel(
    const float* __restrict__ xs,
    const float* __restrict__ noise,
    const int*   __restrict__ inf_start_p,
    float*       __restrict__ out,
    int t, int par)
{
    int b    = blockIdx.x;
    int lane = threadIdx.x;
    const float* __restrict__ th = g_theta[par] + b * PAD;

    float x = (float)t / (float)SEQ;

    // Layer 0: (1 -> 32). W at th[0..31], bias th[32..63].
    float y = x * th[lane] + th[32 + lane];
    y = y / (1.0f + expf(-y));   // silu

    // Hidden layers 1..4: base = 64 + l*1056; W row-major (o,i); bias base+1024.
    #pragma unroll
    for (int l = 0; l < 4; l++) {
        int base = 64 + l * 1056;
        const float4* wp = reinterpret_cast<const float4*>(th + base + lane * 32);
        float4 w[8];
        #pragma unroll
        for (int q = 0; q < 8; q++) w[q] = wp[q];

        float acc = th[base + 1024 + lane];  // bias
        #pragma unroll
        for (int q = 0; q < 8; q++) {
            float yi0 = __shfl_sync(0xffffffffu, y, q * 4 + 0);
            float yi1 = __shfl_sync(0xffffffffu, y, q * 4 + 1);
            float yi2 = __shfl_sync(0xffffffffu, y, q * 4 + 2);
            float yi3 = __shfl_sync(0xffffffffu, y, q * 4 + 3);
            acc = fmaf(w[q].x, yi0, acc);
            acc = fmaf(w[q].y, yi1, acc);
            acc = fmaf(w[q].z, yi2, acc);
            acc = fmaf(w[q].w, yi3, acc);
        }
        y = acc / (1.0f + expf(-acc));  // silu
    }

    // Final layer: (32 -> 2). W at th[4288..4351], bias th[4352..4353].
    float s0 = 0.0f, s1 = 0.0f;
    #pragma unroll
    for (int ii = 0; ii < 32; ii++) {
        float yi = __shfl_sync(0xffffffffu, y, ii);
        s0 = fmaf(yi, th[4288 + ii], s0);
        s1 = fmaf(yi, th[4320 + ii], s1);
    }

    if (lane == 0) {
        float mean = tanhf(s0 + th[4352]);
        float lv   = s1 + th[4353];
        lv = fminf(fmaxf(lv, -4.0f), 4.0f);
        float sd = expf(0.5f * lv);

        out[b * SEQ + t] = mean;
        out[BATCH * SEQ + b * SEQ + t] = sd;

        float nz   = noise[t * BATCH + b];     // noise (seq, batch, 1)
        float xhat = nz * sd + mean;
        float xt   = (t < *inf_start_p) ? xs[b * SEQ + t] : xhat;
        g_u[b]     = xt - g_xprev[b];
        g_xprev[b] = xt;
    }
}

// ---------------------------------------------------------------------------
// Step GEMM: theta_next = clip(theta @ A^T + u * B^T, -1, 1)
// 137 blocks x 256 threads (8 warps/SM, 2/SMSP). Tile 32p x 32b; split-K x2:
// threads [0,128) do k4 0..3 of each chunk, threads [128,256) do k4 4..7.
// Micro-tile 4p x 2b per thread; smem reduction at the end.
// ---------------------------------------------------------------------------
#define DOT4(ac, a, t)                      \
    ac = fmaf((a).x, (t).x, ac);            \
    ac = fmaf((a).y, (t).y, ac);            \
    ac = fmaf((a).z, (t).z, ac);            \
    ac = fmaf((a).w, (t).w, ac);

__global__ __launch_bounds__(256) void gemm_kernel(
    const float* __restrict__ Bv,
    int par)
{
    const float4* __restrict__ th4 = reinterpret_cast<const float4*>(g_theta[par]);
    const float4* __restrict__ A4  = reinterpret_cast<const float4*>(g_A);
    float*        __restrict__ onx = g_theta[par ^ 1];

    __shared__ float4 tS[2][32][9];
    __shared__ float4 aS[2][32][9];
    __shared__ float  red[128][9];   // reduction scratch (padded stride)

    int tid = threadIdx.x;
    int p0  = blockIdx.x * 32;

    // Loader mapping: 256 threads, 1 float4 per array per chunk.
    int r  = tid >> 3;          // 0..31 : row
    int c4 = tid & 7;           // 0..7  : float4 column

    // Compute mapping: low/high half mirror each other on different k4 range.
    int half = tid >> 7;            // 0 or 1
    int ctid = tid & 127;           // 0..127
    int pi   = ctid & 7;            // p = p0 + pi + 8*i
    int bj   = ctid >> 3;           // b = bj, bj+16
    int kbase = half * 4;           // k4 offset within chunk

    float acc[4][2];
    #pragma unroll
    for (int i = 0; i < 4; i++) { acc[i][0] = 0.0f; acc[i][1] = 0.0f; }

    int rowT = r * PAD4;
    int rowA = (p0 + r) * PAD4;

    // Prologue: chunk 0 -> buffer 0.
    {
        tS[0][r][c4] = th4[rowT + c4];
        aS[0][r][c4] = A4[rowA + c4];
    }
    __syncthreads();

    for (int ch = 0; ch < NCH; ch++) {
        int cur = ch & 1;

        // Prefetch next chunk (global -> regs) before compute.
        float4 tPf, aPf;
        bool more = (ch + 1 < NCH);
        if (more) {
            int kb = (ch + 1) * 8 + c4;
            tPf = th4[rowT + kb];
            aPf = A4[rowA + kb];
        }

        // Compute on current buffer: 4 x (6 LDS.128 + 32 FFMA) per thread.
        #pragma unroll
        for (int kk = 0; kk < 4; kk++) {
            int k4 = kbase + kk;
            float4 tv0 = tS[cur][bj][k4];
            float4 tv1 = tS[cur][bj + 16][k4];
            float4 av0 = aS[cur][pi][k4];
            float4 av1 = aS[cur][pi + 8][k4];
            float4 av2 = aS[cur][pi + 16][k4];
            float4 av3 = aS[cur][pi + 24][k4];
            DOT4(acc[0][0], av0, tv0);  DOT4(acc[0][1], av0, tv1);
            DOT4(acc[1][0], av1, tv0);  DOT4(acc[1][1], av1, tv1);
            DOT4(acc[2][0], av2, tv0);  DOT4(acc[2][1], av2, tv1);
            DOT4(acc[3][0], av3, tv0);  DOT4(acc[3][1], av3, tv1);
        }

        // Commit prefetched chunk to the other buffer.
        if (more) {
            int nxt = cur ^ 1;
            tS[nxt][r][c4] = tPf;
            aS[nxt][r][c4] = aPf;
        }
        __syncthreads();
    }

    // Split-K reduction: high half stores, low half adds.
    if (half == 1) {
        #pragma unroll
        for (int i = 0; i < 4; i++) {
            red[ctid][2 * i]     = acc[i][0];
            red[ctid][2 * i + 1] = acc[i][1];
        }
    }
    __syncthreads();

    if (half == 0) {
        // Epilogue: combine halves, rank-1 update + clip + store.
        float u0 = g_u[bj];
        float u1 = g_u[bj + 16];
        #pragma unroll
        for (int i = 0; i < 4; i++) {
            int p = p0 + pi + 8 * i;
            if (p < PDIM) {
                float bp = Bv[p];
                float v0 = acc[i][0] + red[ctid][2 * i];
                float v1 = acc[i][1] + red[ctid][2 * i + 1];
                v0 = fmaf(u0, bp, v0);
                v1 = fmaf(u1, bp, v1);
                v0 = fminf(fmaxf(v0, -1.0f), 1.0f);
                v1 = fminf(fmaxf(v1, -1.0f), 1.0f);
                onx[bj * PAD + p]        = v0;
                onx[(bj + 16) * PAD + p] = v1;
            }
        }
    }
}

// ---------------------------------------------------------------------------
// kernel_launch: init + 64 x (prep, gemm). All graph-capturable launches.
// Inputs: xs(2048) f32, noise(2048) f32, theta_init(4354) f32,
//         A(4354*4354) f32, B(4354) f32, inference_start(1) i32.
// Output: float[4096] = concat(means.T (32,64), stds.T (32,64)).
// ---------------------------------------------------------------------------
extern "C" void kernel_launch(void* const* d_in, const int* in_sizes, int n_in,
                              void* d_out, int out_size) {
    const float* xs         = (const float*)d_in[0];
    const float* noise      = (const float*)d_in[1];
    const float* theta_init = (const float*)d_in[2];
    const float* A          = (const float*)d_in[3];
    const float* Bv         = (const float*)d_in[4];
    const int*   inf_start  = (const int*)d_in[5];
    float*       out        = (float*)d_out;

    init_A_kernel<<<2048, 256>>>(A);
    init_theta_kernel<<<1096, 256>>>(theta_init);

    for (int t = 0; t < SEQ; t++) {
        int par = t & 1;
        prep_kernel<<<BATCH, 32>>>(xs, noise, inf_start, out, t, par);
        gemm_kernel<<<NCH, 256>>>(Bv, par);
    }
}

// round 11
// speedup vs baseline: 2.2194x; 1.2527x over previous
#include <cuda_runtime.h>
#include <cuda_fp16.h>
#include <math.h>
#include <cstdint>

#define PDIM    4354
#define PADK    4480            // K padded: 70 chunks x 64
#define PADP    4480
#define NCHUNK  70
#define NPBLK   137             // 137 x 32 = 4384 >= 4354
#define BATCH   32
#define SEQ     64

// Split scales (Ootomo): v = h + 2^-11 m' + 2^-22 l', all operands fp16-normal.
#define S1F     2048.0f
#define S1I     (1.0f / 2048.0f)
#define S2F     4194304.0f
#define S2I     (1.0f / 4194304.0f)

// smem per buffer (fp16, rows padded to 72 elems = 144 B):
//   Ahi 32x144 | Ami | Alo | Thi | Tmi | Tlo  (each 4608 B)
#define STRIDE_B   144
#define OFF_AHI    0
#define OFF_AMI    4608
#define OFF_ALO    9216
#define OFF_THI    13824
#define OFF_TMI    18432
#define OFF_TLO    23040
#define BUFSZ      27648
#define TILE0      1024
#define SMEM_BYTES (TILE0 + 2 * BUFSZ)   // 56320

// Static device scratch.
__device__ __align__(16) __half g_Ahi[(size_t)PADP * PADK];
__device__ __align__(16) __half g_Ami[(size_t)PADP * PADK];
__device__ __align__(16) __half g_Alo[(size_t)PADP * PADK];
__device__ __align__(16) float  g_theta[2][BATCH * PADK];
__device__ __align__(16) __half g_Thi[2][BATCH * PADK];
__device__ __align__(16) __half g_Tmi[2][BATCH * PADK];
__device__ __align__(16) __half g_Tlo[2][BATCH * PADK];
__device__ float g_u[BATCH];
__device__ float g_xprev[BATCH];

// ---------------------------------------------------------------------------
// PTX helpers (all baseline sm_80+ — safe for the sm_103 (non-'a') ptxas pass)
// ---------------------------------------------------------------------------
__device__ __forceinline__ uint32_t smem_u32(const void* p) {
    uint32_t a;
    asm("{ .reg .u64 t; cvta.to.shared.u64 t, %1; cvt.u32.u64 %0, t; }"
        : "=r"(a) : "l"(p));
    return a;
}
#define CP16(dst, src) \
    asm volatile("cp.async.cg.shared.global [%0], [%1], 16;" :: "r"(dst), "l"(src) : "memory")
#define CP_COMMIT() asm volatile("cp.async.commit_group;" ::: "memory")
#define CP_WAIT1()  asm volatile("cp.async.wait_group 1;" ::: "memory")
#define CP_WAIT0()  asm volatile("cp.async.wait_group 0;" ::: "memory")

#define LDSM4(r0, r1, r2, r3, addr) \
    asm volatile("ldmatrix.sync.aligned.m8n8.x4.shared.b16 {%0,%1,%2,%3}, [%4];" \
                 : "=r"(r0), "=r"(r1), "=r"(r2), "=r"(r3) : "r"(addr))

// In-place accumulate version (used only for the 2^-22-scaled group, where
// the tensor-core RZ alignment bias is negligible after scaling).
#define MMA16816(c, a0, a1, a2, a3, b0, b1) \
    asm volatile("mma.sync.aligned.m16n8k16.row.col.f32.f16.f16.f32 " \
                 "{%0,%1,%2,%3}, {%4,%5,%6,%7}, {%8,%9}, {%0,%1,%2,%3};" \
                 : "+f"((c)[0]), "+f"((c)[1]), "+f"((c)[2]), "+f"((c)[3]) \
                 : "r"(a0), "r"(a1), "r"(a2), "r"(a3), "r"(b0), "r"(b1))

// Zero-C version: D = A*B exactly accumulated over the 16-product tree only;
// the running sum is then added OUTSIDE the tensor core in RN fp32 (no RZ bias).
#define MMA16816_ZC(d, a0, a1, a2, a3, b0, b1) \
    asm volatile("mma.sync.aligned.m16n8k16.row.col.f32.f16.f16.f32 " \
                 "{%0,%1,%2,%3}, {%4,%5,%6,%7}, {%8,%9}, {%10,%10,%10,%10};" \
                 : "=f"((d)[0]), "=f"((d)[1]), "=f"((d)[2]), "=f"((d)[3]) \
                 : "r"(a0), "r"(a1), "r"(a2), "r"(a3), "r"(b0), "r"(b1), "f"(0.0f))

#define ACC4(c, d) \
    (c)[0] += (d)[0]; (c)[1] += (d)[1]; (c)[2] += (d)[2]; (c)[3] += (d)[3];

// Scaled 3-split: v = h + S1I*m + S2I*l ; h, m, l all in fp16 NORMAL range.
__device__ __forceinline__ void split3s(float v, __half& h, __half& m, __half& l) {
    h = __float2half_rn(v);
    float r1 = v - __half2float(h);
    m = __float2half_rn(r1 * S1F);
    float r2 = r1 - __half2float(m) * S1I;
    l = __float2half_rn(r2 * S2F);
}

// ---------------------------------------------------------------------------
// Init 1: scaled 3-split of A -> fp16 hi/mid/lo, zero-padded to PADP x PADK.
// ---------------------------------------------------------------------------
__global__ void init_A_kernel(const float* __restrict__ A) {
    size_t total = (size_t)PADP * PADK;
    for (size_t idx = blockIdx.x * (size_t)blockDim.x + threadIdx.x;
         idx < total; idx += (size_t)gridDim.x * blockDim.x) {
        int p = (int)(idx / PADK);
        int k = (int)(idx - (size_t)p * PADK);
        float a = (p < PDIM && k < PDIM) ? A[(size_t)p * PDIM + k] : 0.0f;
        __half h, m, l;
        split3s(a, h, m, l);
        g_Ahi[idx] = h;
        g_Ami[idx] = m;
        g_Alo[idx] = l;
    }
}

// ---------------------------------------------------------------------------
// Init 2: theta fp32 + scaled 3-splits (buf0 = theta_init, buf1 = 0).
// ---------------------------------------------------------------------------
__global__ void init_theta_kernel(const float* __restrict__ theta_init) {
    int total = 2 * BATCH * PADK;
    for (int idx = blockIdx.x * blockDim.x + threadIdx.x;
         idx < total; idx += gridDim.x * blockDim.x) {
        int buf = idx / (BATCH * PADK);
        int k = (idx - buf * (BATCH * PADK)) % PADK;
        float v = (buf == 0 && k < PDIM) ? theta_init[k] : 0.0f;
        __half h, m, l;
        split3s(v, h, m, l);
        ((float*)g_theta)[idx] = v;
        ((__half*)g_Thi)[idx]  = h;
        ((__half*)g_Tmi)[idx]  = m;
        ((__half*)g_Tlo)[idx]  = l;
    }
    int i0 = blockIdx.x * blockDim.x + threadIdx.x;
    if (i0 < BATCH) g_xprev[i0] = 0.0f;
}

// ---------------------------------------------------------------------------
// Prep kernel: one block per batch; tiny 5-layer MLP + carry update.
// ---------------------------------------------------------------------------
__global__ __launch_bounds__(32) void prep_kernel(
    const float* __restrict__ xs,
    const float* __restrict__ noise,
    const int*   __restrict__ inf_start_p,
    float*       __restrict__ out,
    int t, int par)
{
    int b    = blockIdx.x;
    int lane = threadIdx.x;
    const float* __restrict__ th = g_theta[par] + b * PADK;

    float x = (float)t / (float)SEQ;
    float y = x * th[lane] + th[32 + lane];
    y = y / (1.0f + expf(-y));

    #pragma unroll
    for (int l = 0; l < 4; l++) {
        int base = 64 + l * 1056;
        const float4* wp = reinterpret_cast<const float4*>(th + base + lane * 32);
        float4 w[8];
        #pragma unroll
        for (int q = 0; q < 8; q++) w[q] = wp[q];
        float acc = th[base + 1024 + lane];
        #pragma unroll
        for (int q = 0; q < 8; q++) {
            float y0 = __shfl_sync(0xffffffffu, y, q * 4 + 0);
            float y1 = __shfl_sync(0xffffffffu, y, q * 4 + 1);
            float y2 = __shfl_sync(0xffffffffu, y, q * 4 + 2);
            float y3 = __shfl_sync(0xffffffffu, y, q * 4 + 3);
            acc = fmaf(w[q].x, y0, acc);
            acc = fmaf(w[q].y, y1, acc);
            acc = fmaf(w[q].z, y2, acc);
            acc = fmaf(w[q].w, y3, acc);
        }
        y = acc / (1.0f + expf(-acc));
    }

    float s0 = 0.0f, s1 = 0.0f;
    #pragma unroll
    for (int ii = 0; ii < 32; ii++) {
        float yi = __shfl_sync(0xffffffffu, y, ii);
        s0 = fmaf(yi, th[4288 + ii], s0);
        s1 = fmaf(yi, th[4320 + ii], s1);
    }

    if (lane == 0) {
        float mean = tanhf(s0 + th[4352]);
        float lv   = fminf(fmaxf(s1 + th[4353], -4.0f), 4.0f);
        float sd   = expf(0.5f * lv);
        out[b * SEQ + t] = mean;
        out[BATCH * SEQ + b * SEQ + t] = sd;
        float nz   = noise[t * BATCH + b];
        float xhat = nz * sd + mean;
        float xt   = (t < *inf_start_p) ? xs[b * SEQ + t] : xhat;
        g_u[b]     = xt - g_xprev[b];
        g_xprev[b] = xt;
    }
}

// ---------------------------------------------------------------------------
// GEMM step: theta_next = clip(theta @ A^T + u*B^T, -1, 1) via mma.sync fp16
// Scaled 3-split operands, 3 accumulator groups:
//   acc0 = hh (zero-C mma + external RN fp32 adds — no RZ bias)
//   acc1 = hm + mh (zero-C + external adds)
//   acc2 = hl + lh + mm (in-mma accumulate; bias scaled by 2^-22)
//   result = acc0 + 2^-11 acc1 + 2^-22 acc2
// 137 CTAs x 256 thr. CTA tile: 32p x 32b, K in 70 chunks of 64.
// Warp w: P-group pg=w&1 (16 rows), K-quarter kh=w>>1 (16 of 64 chunk cols).
// ---------------------------------------------------------------------------
__device__ __forceinline__ void issue_chunk(int j, uint32_t sb, int tid, int p0, int par) {
    uint32_t buf = sb + TILE0 + (j & 1) * BUFSZ;
    int kbase = j * 64;
    int r = tid >> 3, s = tid & 7;               // 32 rows x 8 segs
    uint32_t off = buf + r * STRIDE_B + s * 16;
    size_t ga = (size_t)(p0 + r) * PADK + kbase + s * 8;
    CP16(off + OFF_AHI, g_Ahi + ga);
    CP16(off + OFF_AMI, g_Ami + ga);
    CP16(off + OFF_ALO, g_Alo + ga);
    size_t gt = (size_t)r * PADK + kbase + s * 8;
    CP16(off + OFF_THI, g_Thi[par] + gt);
    CP16(off + OFF_TMI, g_Tmi[par] + gt);
    CP16(off + OFF_TLO, g_Tlo[par] + gt);
}

__global__ __launch_bounds__(256) void gemm_kernel(const float* __restrict__ Bv, int par) {
    extern __shared__ char smem[];
    uint32_t sb = smem_u32(smem);
    int tid  = threadIdx.x;
    int wid  = tid >> 5;
    int lane = tid & 31;
    int pg   = wid & 1;          // P-group (16 rows)
    int kh   = wid >> 1;         // K-quarter (16 cols of each 64 chunk)
    int p0   = blockIdx.x * 32;

    float* u_s  = (float*)smem;          // [32]
    float* bv_s = (float*)smem + 32;     // [32]
    if (tid < 32) u_s[tid] = g_u[tid];
    if (tid >= 64 && tid < 96) {
        int i = tid - 64;
        int p = p0 + i;
        bv_s[i] = (p < PDIM) ? Bv[p] : 0.0f;
    }

    float acc0[4][4], acc1[4][4], acc2[4][4];
    #pragma unroll
    for (int nt = 0; nt < 4; nt++)
        #pragma unroll
        for (int j = 0; j < 4; j++) {
            acc0[nt][j] = 0.0f; acc1[nt][j] = 0.0f; acc2[nt][j] = 0.0f;
        }

    int aRow  = pg * 16 + (lane & 15);
    int aKoff = (lane >> 4) * 8;
    int krel  = kh * 16;

    issue_chunk(0, sb, tid, p0, par);
    CP_COMMIT();

    for (int ch = 0; ch < NCHUNK; ch++) {
        if (ch + 1 < NCHUNK) {
            issue_chunk(ch + 1, sb, tid, p0, par);
            CP_COMMIT();
            CP_WAIT1();
        } else {
            CP_WAIT0();
        }
        __syncthreads();

        uint32_t buf = sb + TILE0 + (ch & 1) * BUFSZ;

        uint32_t aAddr = buf + aRow * STRIDE_B + (krel + aKoff) * 2;
        uint32_t ah0, ah1, ah2, ah3, am0, am1, am2, am3, al0, al1, al2, al3;
        LDSM4(ah0, ah1, ah2, ah3, aAddr + OFF_AHI);
        LDSM4(am0, am1, am2, am3, aAddr + OFF_AMI);
        LDSM4(al0, al1, al2, al3, aAddr + OFF_ALO);

        uint32_t tAddr = buf + lane * STRIDE_B + krel * 2;
        uint32_t bh0[4], bh8[4], bm0[4], bm8[4], bl0[4], bl8[4];
        LDSM4(bh0[0], bh0[1], bh0[2], bh0[3], tAddr + OFF_THI);
        LDSM4(bh8[0], bh8[1], bh8[2], bh8[3], tAddr + OFF_THI + 16);
        LDSM4(bm0[0], bm0[1], bm0[2], bm0[3], tAddr + OFF_TMI);
        LDSM4(bm8[0], bm8[1], bm8[2], bm8[3], tAddr + OFF_TMI + 16);
        LDSM4(bl0[0], bl0[1], bl0[2], bl0[3], tAddr + OFF_TLO);
        LDSM4(bl8[0], bl8[1], bl8[2], bl8[3], tAddr + OFF_TLO + 16);

        #pragma unroll
        for (int nt = 0; nt < 4; nt++) {
            float d[4];
            MMA16816_ZC(d, ah0, ah1, ah2, ah3, bh0[nt], bh8[nt]);   // hh
            ACC4(acc0[nt], d);
            MMA16816_ZC(d, ah0, ah1, ah2, ah3, bm0[nt], bm8[nt]);   // hm
            ACC4(acc1[nt], d);
            MMA16816_ZC(d, am0, am1, am2, am3, bh0[nt], bh8[nt]);   // mh
            ACC4(acc1[nt], d);
            MMA16816(acc2[nt], ah0, ah1, ah2, ah3, bl0[nt], bl8[nt]);  // hl
            MMA16816(acc2[nt], al0, al1, al2, al3, bh0[nt], bh8[nt]);  // lh
            MMA16816(acc2[nt], am0, am1, am2, am3, bm0[nt], bm8[nt]);  // mm
        }
        __syncthreads();
    }

    // Combine scale groups per element, then split-K x4 reduction.
    float loc[4][4];
    #pragma unroll
    for (int nt = 0; nt < 4; nt++)
        #pragma unroll
        for (int j = 0; j < 4; j++)
            loc[nt][j] = acc0[nt][j] + (S1I * acc1[nt][j] + S2I * acc2[nt][j]);

    float* red = (float*)(smem + TILE0);   // [3][32 r][32 c] = 12 KB
    int r   = lane >> 2;
    int cpr = (lane & 3) * 2;

    if (kh > 0) {
        float* rd = red + (kh - 1) * 1024;
        #pragma unroll
        for (int nt = 0; nt < 4; nt++) {
            int c = nt * 8 + cpr;
            rd[(pg * 16 + r) * 32 + c]         = loc[nt][0];
            rd[(pg * 16 + r) * 32 + c + 1]     = loc[nt][1];
            rd[(pg * 16 + r + 8) * 32 + c]     = loc[nt][2];
            rd[(pg * 16 + r + 8) * 32 + c + 1] = loc[nt][3];
        }
    }
    __syncthreads();

    if (kh == 0) {
        float*  oF = g_theta[par ^ 1];
        __half* oH = g_Thi[par ^ 1];
        __half* oM = g_Tmi[par ^ 1];
        __half* oL = g_Tlo[par ^ 1];
        #pragma unroll
        for (int nt = 0; nt < 4; nt++) {
            int c = nt * 8 + cpr;
            #pragma unroll
            for (int j = 0; j < 4; j++) {
                int rr = (j >> 1) ? r + 8 : r;
                int cc = c + (j & 1);
                int lr = pg * 16 + rr;
                int p  = p0 + lr;
                if (p < PDIM) {
                    float v = loc[nt][j]
                            + red[lr * 32 + cc]
                            + red[1024 + lr * 32 + cc]
                            + red[2048 + lr * 32 + cc];
                    v = fmaf(u_s[cc], bv_s[lr], v);
                    v = fminf(fmaxf(v, -1.0f), 1.0f);
                    __half h, m, l;
                    split3s(v, h, m, l);
                    size_t o = (size_t)cc * PADK + p;
                    oF[o] = v;
                    oH[o] = h;
                    oM[o] = m;
                    oL[o] = l;
                }
            }
        }
    }
}

// ---------------------------------------------------------------------------
// kernel_launch
// ---------------------------------------------------------------------------
extern "C" void kernel_launch(void* const* d_in, const int* in_sizes, int n_in,
                              void* d_out, int out_size) {
    const float* xs         = (const float*)d_in[0];
    const float* noise      = (const float*)d_in[1];
    const float* theta_init = (const float*)d_in[2];
    const float* A          = (const float*)d_in[3];
    const float* Bv         = (const float*)d_in[4];
    const int*   inf_start  = (const int*)d_in[5];
    float*       out        = (float*)d_out;

    cudaFuncSetAttribute(gemm_kernel,
                         cudaFuncAttributeMaxDynamicSharedMemorySize, SMEM_BYTES);

    init_A_kernel<<<4096, 256>>>(A);
    init_theta_kernel<<<1120, 256>>>(theta_init);

    for (int t = 0; t < SEQ; t++) {
        int par = t & 1;
        prep_kernel<<<BATCH, 32>>>(xs, noise, inf_start, out, t, par);
        gemm_kernel<<<NPBLK, 256, SMEM_BYTES>>>(Bv, par);
    }
}

// round 12
// speedup vs baseline: 3.5272x; 1.5893x over previous
#include <cuda_runtime.h>
#include <cuda_fp16.h>
#include <math.h>
#include <cstdint>

#define PDIM    4354
#define PADK    4480            // K padded: 70 chunks x 64
#define PADP    4480
#define NCHUNK  70
#define NPBLK   137             // 137 x 32 = 4384 >= 4354
#define BATCH   32
#define SEQ     64

// Split scales (Ootomo): v = h + 2^-11 m', both operands fp16-normal.
// Residual after the 2-split is <= |v| * 2^-24 -> negligible through the GEMM.
#define S1F     2048.0f
#define S1I     (1.0f / 2048.0f)

// smem per buffer (fp16, rows padded to 72 elems = 144 B):
//   Ahi 32x144 | Ami | Thi | Tmi  (each 4608 B) = 18432 B; 4-stage pipeline.
#define STRIDE_B   144
#define OFF_AHI    0
#define OFF_AMI    4608
#define OFF_THI    9216
#define OFF_TMI    13824
#define BUFSZ      18432
#define NBUF       4
#define TILE0      1024
#define SMEM_BYTES (TILE0 + NBUF * BUFSZ)   // 74752

// Static device scratch.
__device__ __align__(16) __half g_Ahi[(size_t)PADP * PADK];
__device__ __align__(16) __half g_Ami[(size_t)PADP * PADK];
__device__ __align__(16) float  g_theta[2][BATCH * PADK];
__device__ __align__(16) __half g_Thi[2][BATCH * PADK];
__device__ __align__(16) __half g_Tmi[2][BATCH * PADK];
__device__ float g_u[BATCH];
__device__ float g_xprev[BATCH];

// ---------------------------------------------------------------------------
// PTX helpers (all baseline sm_80+ — safe for the sm_103 (non-'a') ptxas pass)
// ---------------------------------------------------------------------------
__device__ __forceinline__ uint32_t smem_u32(const void* p) {
    uint32_t a;
    asm("{ .reg .u64 t; cvta.to.shared.u64 t, %1; cvt.u32.u64 %0, t; }"
        : "=r"(a) : "l"(p));
    return a;
}
#define CP16(dst, src) \
    asm volatile("cp.async.cg.shared.global [%0], [%1], 16;" :: "r"(dst), "l"(src) : "memory")
#define CP_COMMIT() asm volatile("cp.async.commit_group;" ::: "memory")
#define CP_WAIT3()  asm volatile("cp.async.wait_group 3;" ::: "memory")
#define CP_WAIT0()  asm volatile("cp.async.wait_group 0;" ::: "memory")

#define LDSM4(r0, r1, r2, r3, addr) \
    asm volatile("ldmatrix.sync.aligned.m8n8.x4.shared.b16 {%0,%1,%2,%3}, [%4];" \
                 : "=r"(r0), "=r"(r1), "=r"(r2), "=r"(r3) : "r"(addr))

// In-mma accumulate (used for the 2^-11-scaled group: RZ bias enters * 2^-11).
#define MMA16816(c, a0, a1, a2, a3, b0, b1) \
    asm volatile("mma.sync.aligned.m16n8k16.row.col.f32.f16.f16.f32 " \
                 "{%0,%1,%2,%3}, {%4,%5,%6,%7}, {%8,%9}, {%0,%1,%2,%3};" \
                 : "+f"((c)[0]), "+f"((c)[1]), "+f"((c)[2]), "+f"((c)[3]) \
                 : "r"(a0), "r"(a1), "r"(a2), "r"(a3), "r"(b0), "r"(b1))

// Zero-C version: running sum added OUTSIDE the tensor core (RN fp32, no bias).
#define MMA16816_ZC(d, a0, a1, a2, a3, b0, b1) \
    asm volatile("mma.sync.aligned.m16n8k16.row.col.f32.f16.f16.f32 " \
                 "{%0,%1,%2,%3}, {%4,%5,%6,%7}, {%8,%9}, {%10,%10,%10,%10};" \
                 : "=f"((d)[0]), "=f"((d)[1]), "=f"((d)[2]), "=f"((d)[3]) \
                 : "r"(a0), "r"(a1), "r"(a2), "r"(a3), "r"(b0), "r"(b1), "f"(0.0f))

#define ACC4(c, d) \
    (c)[0] += (d)[0]; (c)[1] += (d)[1]; (c)[2] += (d)[2]; (c)[3] += (d)[3];

// Scaled 2-split: v = h + S1I*m ; h, m in fp16 NORMAL range.
__device__ __forceinline__ void split2s(float v, __half& h, __half& m) {
    h = __float2half_rn(v);
    m = __float2half_rn((v - __half2float(h)) * S1F);
}

// ---------------------------------------------------------------------------
// Init 1: scaled 2-split of A -> fp16 hi/mid, zero-padded to PADP x PADK.
// ---------------------------------------------------------------------------
__global__ void init_A_kernel(const float* __restrict__ A) {
    size_t total = (size_t)PADP * PADK;
    for (size_t idx = blockIdx.x * (size_t)blockDim.x + threadIdx.x;
         idx < total; idx += (size_t)gridDim.x * blockDim.x) {
        int p = (int)(idx / PADK);
        int k = (int)(idx - (size_t)p * PADK);
        float a = (p < PDIM && k < PDIM) ? A[(size_t)p * PDIM + k] : 0.0f;
        __half h, m;
        split2s(a, h, m);
        g_Ahi[idx] = h;
        g_Ami[idx] = m;
    }
}

// ---------------------------------------------------------------------------
// Init 2: theta fp32 + scaled 2-splits (buf0 = theta_init, buf1 = 0).
// ---------------------------------------------------------------------------
__global__ void init_theta_kernel(const float* __restrict__ theta_init) {
    int total = 2 * BATCH * PADK;
    for (int idx = blockIdx.x * blockDim.x + threadIdx.x;
         idx < total; idx += gridDim.x * blockDim.x) {
        int buf = idx / (BATCH * PADK);
        int k = (idx - buf * (BATCH * PADK)) % PADK;
        float v = (buf == 0 && k < PDIM) ? theta_init[k] : 0.0f;
        __half h, m;
        split2s(v, h, m);
        ((float*)g_theta)[idx] = v;
        ((__half*)g_Thi)[idx]  = h;
        ((__half*)g_Tmi)[idx]  = m;
    }
    int i0 = blockIdx.x * blockDim.x + threadIdx.x;
    if (i0 < BATCH) g_xprev[i0] = 0.0f;
}

// ---------------------------------------------------------------------------
// Prep kernel: one block per batch; tiny 5-layer MLP + carry update.
// ---------------------------------------------------------------------------
__global__ __launch_bounds__(32) void prep_kernel(
    const float* __restrict__ xs,
    const float* __restrict__ noise,
    const int*   __restrict__ inf_start_p,
    float*       __restrict__ out,
    int t, int par)
{
    int b    = blockIdx.x;
    int lane = threadIdx.x;
    const float* __restrict__ th = g_theta[par] + b * PADK;

    float x = (float)t / (float)SEQ;
    float y = x * th[lane] + th[32 + lane];
    y = y / (1.0f + expf(-y));

    #pragma unroll
    for (int l = 0; l < 4; l++) {
        int base = 64 + l * 1056;
        const float4* wp = reinterpret_cast<const float4*>(th + base + lane * 32);
        float4 w[8];
        #pragma unroll
        for (int q = 0; q < 8; q++) w[q] = wp[q];
        float acc = th[base + 1024 + lane];
        #pragma unroll
        for (int q = 0; q < 8; q++) {
            float y0 = __shfl_sync(0xffffffffu, y, q * 4 + 0);
            float y1 = __shfl_sync(0xffffffffu, y, q * 4 + 1);
            float y2 = __shfl_sync(0xffffffffu, y, q * 4 + 2);
            float y3 = __shfl_sync(0xffffffffu, y, q * 4 + 3);
            acc = fmaf(w[q].x, y0, acc);
            acc = fmaf(w[q].y, y1, acc);
            acc = fmaf(w[q].z, y2, acc);
            acc = fmaf(w[q].w, y3, acc);
        }
        y = acc / (1.0f + expf(-acc));
    }

    float s0 = 0.0f, s1 = 0.0f;
    #pragma unroll
    for (int ii = 0; ii < 32; ii++) {
        float yi = __shfl_sync(0xffffffffu, y, ii);
        s0 = fmaf(yi, th[4288 + ii], s0);
        s1 = fmaf(yi, th[4320 + ii], s1);
    }

    if (lane == 0) {
        float mean = tanhf(s0 + th[4352]);
        float lv   = fminf(fmaxf(s1 + th[4353], -4.0f), 4.0f);
        float sd   = expf(0.5f * lv);
        out[b * SEQ + t] = mean;
        out[BATCH * SEQ + b * SEQ + t] = sd;
        float nz   = noise[t * BATCH + b];
        float xhat = nz * sd + mean;
        float xt   = (t < *inf_start_p) ? xs[b * SEQ + t] : xhat;
        g_u[b]     = xt - g_xprev[b];
        g_xprev[b] = xt;
    }
}

// ---------------------------------------------------------------------------
// GEMM step: theta_next = clip(theta @ A^T + u*B^T, -1, 1) via mma.sync fp16
// Scaled 2-split operands, 2 accumulator groups:
//   acc0 = hh (zero-C mma + external RN adds)   acc1 = hm + mh (in-mma)
//   result = acc0 + 2^-11 acc1   (residual terms ~2^-24, dropped)
// 137 CTAs x 256 thr, 4-stage cp.async pipeline.
// Warp w: P-group pg=w&1 (16 rows), K-quarter kh=w>>1 (16 of 64 chunk cols).
// ---------------------------------------------------------------------------
__device__ __forceinline__ void issue_chunk(int j, uint32_t sb, int tid, int p0, int par) {
    uint32_t buf = sb + TILE0 + (j & (NBUF - 1)) * BUFSZ;
    int kbase = j * 64;
    int r = tid >> 3, s = tid & 7;               // 32 rows x 8 segs
    uint32_t off = buf + r * STRIDE_B + s * 16;
    size_t ga = (size_t)(p0 + r) * PADK + kbase + s * 8;
    CP16(off + OFF_AHI, g_Ahi + ga);
    CP16(off + OFF_AMI, g_Ami + ga);
    size_t gt = (size_t)r * PADK + kbase + s * 8;
    CP16(off + OFF_THI, g_Thi[par] + gt);
    CP16(off + OFF_TMI, g_Tmi[par] + gt);
}

__global__ __launch_bounds__(256) void gemm_kernel(const float* __restrict__ Bv, int par) {
    extern __shared__ char smem[];
    uint32_t sb = smem_u32(smem);
    int tid  = threadIdx.x;
    int wid  = tid >> 5;
    int lane = tid & 31;
    int pg   = wid & 1;          // P-group (16 rows)
    int kh   = wid >> 1;         // K-quarter (16 cols of each 64 chunk)
    int p0   = blockIdx.x * 32;

    float* u_s  = (float*)smem;          // [32]
    float* bv_s = (float*)smem + 32;     // [32]
    if (tid < 32) u_s[tid] = g_u[tid];
    if (tid >= 64 && tid < 96) {
        int i = tid - 64;
        int p = p0 + i;
        bv_s[i] = (p < PDIM) ? Bv[p] : 0.0f;
    }

    float acc0[4][4], acc1[4][4];
    #pragma unroll
    for (int nt = 0; nt < 4; nt++)
        #pragma unroll
        for (int j = 0; j < 4; j++) { acc0[nt][j] = 0.0f; acc1[nt][j] = 0.0f; }

    int aRow  = pg * 16 + (lane & 15);
    int aKoff = (lane >> 4) * 8;
    int krel  = kh * 16;

    // Prologue: fill 3 stages.
    issue_chunk(0, sb, tid, p0, par); CP_COMMIT();
    issue_chunk(1, sb, tid, p0, par); CP_COMMIT();
    issue_chunk(2, sb, tid, p0, par); CP_COMMIT();

    for (int ch = 0; ch < NCHUNK; ch++) {
        if (ch + 3 < NCHUNK) issue_chunk(ch + 3, sb, tid, p0, par);
        CP_COMMIT();            // empty group when past the end — keeps count uniform
        CP_WAIT3();             // chunk ch's group complete
        __syncthreads();

        uint32_t buf = sb + TILE0 + (ch & (NBUF - 1)) * BUFSZ;

        uint32_t aAddr = buf + aRow * STRIDE_B + (krel + aKoff) * 2;
        uint32_t ah0, ah1, ah2, ah3, am0, am1, am2, am3;
        LDSM4(ah0, ah1, ah2, ah3, aAddr + OFF_AHI);
        LDSM4(am0, am1, am2, am3, aAddr + OFF_AMI);

        uint32_t tAddr = buf + lane * STRIDE_B + krel * 2;
        uint32_t bh0[4], bh8[4], bm0[4], bm8[4];
        LDSM4(bh0[0], bh0[1], bh0[2], bh0[3], tAddr + OFF_THI);
        LDSM4(bh8[0], bh8[1], bh8[2], bh8[3], tAddr + OFF_THI + 16);
        LDSM4(bm0[0], bm0[1], bm0[2], bm0[3], tAddr + OFF_TMI);
        LDSM4(bm8[0], bm8[1], bm8[2], bm8[3], tAddr + OFF_TMI + 16);

        #pragma unroll
        for (int nt = 0; nt < 4; nt++) {
            float d[4];
            MMA16816_ZC(d, ah0, ah1, ah2, ah3, bh0[nt], bh8[nt]);       // hh
            ACC4(acc0[nt], d);
            MMA16816(acc1[nt], ah0, ah1, ah2, ah3, bm0[nt], bm8[nt]);   // hm
            MMA16816(acc1[nt], am0, am1, am2, am3, bh0[nt], bh8[nt]);   // mh
        }
        __syncthreads();
    }

    // Combine scale groups, then split-K x4 reduction.
    float loc[4][4];
    #pragma unroll
    for (int nt = 0; nt < 4; nt++)
        #pragma unroll
        for (int j = 0; j < 4; j++)
            loc[nt][j] = fmaf(S1I, acc1[nt][j], acc0[nt][j]);

    float* red = (float*)(smem + TILE0);   // [3][32 r][32 c] = 12 KB (reuses bufs)
    int r   = lane >> 2;
    int cpr = (lane & 3) * 2;

    if (kh > 0) {
        float* rd = red + (kh - 1) * 1024;
        #pragma unroll
        for (int nt = 0; nt < 4; nt++) {
            int c = nt * 8 + cpr;
            rd[(pg * 16 + r) * 32 + c]         = loc[nt][0];
            rd[(pg * 16 + r) * 32 + c + 1]     = loc[nt][1];
            rd[(pg * 16 + r + 8) * 32 + c]     = loc[nt][2];
            rd[(pg * 16 + r + 8) * 32 + c + 1] = loc[nt][3];
        }
    }
    __syncthreads();

    if (kh == 0) {
        float*  oF = g_theta[par ^ 1];
        __half* oH = g_Thi[par ^ 1];
        __half* oM = g_Tmi[par ^ 1];
        #pragma unroll
        for (int nt = 0; nt < 4; nt++) {
            int c = nt * 8 + cpr;
            #pragma unroll
            for (int j = 0; j < 4; j++) {
                int rr = (j >> 1) ? r + 8 : r;
                int cc = c + (j & 1);
                int lr = pg * 16 + rr;
                int p  = p0 + lr;
                if (p < PDIM) {
                    float v = loc[nt][j]
                            + red[lr * 32 + cc]
                            + red[1024 + lr * 32 + cc]
                            + red[2048 + lr * 32 + cc];
                    v = fmaf(u_s[cc], bv_s[lr], v);
                    v = fminf(fmaxf(v, -1.0f), 1.0f);
                    __half h, m;
                    split2s(v, h, m);
                    size_t o = (size_t)cc * PADK + p;
                    oF[o] = v;
                    oH[o] = h;
                    oM[o] = m;
                }
            }
        }
    }
}

// ---------------------------------------------------------------------------
// kernel_launch
// ---------------------------------------------------------------------------
extern "C" void kernel_launch(void* const* d_in, const int* in_sizes, int n_in,
                              void* d_out, int out_size) {
    const float* xs         = (const float*)d_in[0];
    const float* noise      = (const float*)d_in[1];
    const float* theta_init = (const float*)d_in[2];
    const float* A          = (const float*)d_in[3];
    const float* Bv         = (const float*)d_in[4];
    const int*   inf_start  = (const int*)d_in[5];
    float*       out        = (float*)d_out;

    cudaFuncSetAttribute(gemm_kernel,
                         cudaFuncAttributeMaxDynamicSharedMemorySize, SMEM_BYTES);

    init_A_kernel<<<4096, 256>>>(A);
    init_theta_kernel<<<1120, 256>>>(theta_init);

    for (int t = 0; t < SEQ; t++) {
        int par = t & 1;
        prep_kernel<<<BATCH, 32>>>(xs, noise, inf_start, out, t, par);
        gemm_kernel<<<NPBLK, 256, SMEM_BYTES>>>(Bv, par);
    }
}